// round 6
// baseline (speedup 1.0000x reference)
#include <cuda_runtime.h>

// GRU_83906481094863 — fused persistent GRU on sm_100a, v5 (resubmit after infra fail).
// v2 layout (best so far) + crossbar/FMA overlap fix + cheap nonlinearities.
// B=512, T=1024, D=46, H=128. 128 CTAs x 192 threads, NB=4 batches/CTA.
//   threads [0,128): gate threads (4 warps, 1/SMSP). Thread u owns gate rows
//     {u, u+128, u+256} -> full (r,z,n) of hidden unit u in register.
//     hh-dot (smem W, LDS.128) and ih-dot (register W) are FUSED in one loop
//     so x-FMAs (no smem dependence) hide W/h crossbar queueing.
//   threads [128,192): aux, prefetch x(t+1). ONE __syncthreads per step.
// Nonlinearities via __expf + __fdividef (MUFU; rel err ~1e-6 << 1e-3 budget).

#define BB 512
#define TT 1024
#define DD 46
#define DP 48
#define HH 128
#define GG 384
#define NB 4
#define NCTA (BB/NB) // 128
#define NTHR 192
#define NGATE 128

// Shared (floats): sW[49152] W_hh k-chunk-major; sH[2][NB][HH]=1024; sX[2][NB][DP]=384
#define SMEM_FLOATS (49152 + 1024 + 384)
#define SMEM_BYTES  (SMEM_FLOATS * 4)

__device__ __forceinline__ void fma2(unsigned long long &d,
                                     unsigned long long a,
                                     unsigned long long b) {
    asm("fma.rn.f32x2 %0, %1, %2, %0;" : "+l"(d) : "l"(a), "l"(b));
}
__device__ __forceinline__ float sum2(unsigned long long v) {
    float lo, hi;
    asm("mov.b64 {%0, %1}, %2;" : "=f"(lo), "=f"(hi) : "l"(v));
    return lo + hi;
}
__device__ __forceinline__ unsigned long long pack2(float lo, float hi) {
    unsigned long long v;
    asm("mov.b64 %0, {%1, %2};" : "=l"(v) : "f"(lo), "f"(hi));
    return v;
}
// sigmoid: 1/(1+e^-x). e=inf -> returns 0 (correct limit). MUFU.EX2 + RCP.
__device__ __forceinline__ float fast_sig(float x) {
    float e = __expf(-x);
    return __fdividef(1.f, 1.f + e);
}
// tanh: (1-e)/(1+e), e=e^-2x, input clamped so e stays finite.
__device__ __forceinline__ float fast_tanh(float x) {
    x = fminf(15.f, fmaxf(-15.f, x));
    float e = __expf(-2.f * x);
    return __fdividef(1.f - e, 1.f + e);
}

__global__ void __launch_bounds__(NTHR, 1) gru_fused_v5(
    const float* __restrict__ history,  // [B][T][D]
    const float* __restrict__ W_ih,     // [3H][D]
    const float* __restrict__ W_hh,     // [3H][H]
    const float* __restrict__ b_ih,     // [3H]
    const float* __restrict__ b_hh,     // [3H]
    const float* __restrict__ h0,       // [H]
    float* __restrict__ out)            // [B][H]
{
    extern __shared__ float smem[];
    float* sW = smem;            // float4 view: (kc*GG + j)
    float* sH = smem + 49152;    // [2][NB][HH]
    float* sX = sH + 1024;       // [2][NB][DP]

    const int tid = threadIdx.x;
    const int b0  = blockIdx.x * NB;

    // ---- stage W_hh k-chunk-major ----
    for (int idx = tid; idx < GG * HH; idx += NTHR) {
        int j = idx >> 7, k = idx & 127;
        sW[((k >> 2) * GG + j) * 4 + (k & 3)] = W_hh[idx];
    }
    // ---- h(0) ----
    for (int idx = tid; idx < NB * HH; idx += NTHR)
        sH[idx] = h0[idx & 127];
    // ---- zero x pads ----
    if (tid < 16) {
        int buf = tid >> 3, nb = (tid >> 1) & 3, d = DD + (tid & 1);
        sX[buf * (NB * DP) + nb * DP + d] = 0.f;
    }
    // ---- x(0) ----
    for (int idx = tid; idx < NB * DD; idx += NTHR) {
        int nb = idx / DD, d = idx - nb * DD;
        sX[nb * DP + d] = history[(size_t)(b0 + nb) * (TT * DD) + d];
    }

    // ---- gate-thread private state ----
    const int u = tid;
    unsigned long long wih[3][24];
    float bi[3], bh[3];
    if (tid < NGATE) {
        #pragma unroll
        for (int g = 0; g < 3; g++) {
            const int j = u + g * HH;
            bi[g] = b_ih[j];
            bh[g] = b_hh[j];
            #pragma unroll
            for (int p = 0; p < 23; p++)
                wih[g][p] = pack2(W_ih[j * DD + 2 * p], W_ih[j * DD + 2 * p + 1]);
            wih[g][23] = 0ull;
        }
    }
    const ulonglong2* wrow0 = (const ulonglong2*)sW + u;           // row u
    const ulonglong2* wrow1 = wrow0 + HH;                          // row u+128
    const ulonglong2* wrow2 = wrow0 + 2 * HH;                      // row u+256

    __syncthreads();

    for (int t = 0; t < TT; t++) {
        const int cur = t & 1, nxt = cur ^ 1;

        if (tid < NGATE) {
            const float* hb = sH + cur * (NB * HH);
            const float* xb = sX + cur * (NB * DP);

            unsigned long long ah[3][NB], ai[3][NB];
            #pragma unroll
            for (int g = 0; g < 3; g++)
                #pragma unroll
                for (int nb = 0; nb < NB; nb++) { ah[g][nb] = 0ull; ai[g][nb] = 0ull; }

            // ---- FUSED loop: 16 iters, each = 2 hh k-chunks (+1 x-chunk if i<12)
            // x-FMAs use register weights only -> independent issue stream that
            // keeps the FMA pipe busy while W/h loads queue on the crossbar.
            #pragma unroll 8
            for (int i = 0; i < 16; i++) {
                #pragma unroll
                for (int s = 0; s < 2; s++) {
                    const int kc = 2 * i + s;
                    ulonglong2 w0 = wrow0[kc * GG];
                    ulonglong2 w1 = wrow1[kc * GG];
                    ulonglong2 w2 = wrow2[kc * GG];
                    ulonglong2 hA = *(const ulonglong2*)(hb + 0 * HH + kc * 4);
                    ulonglong2 hB = *(const ulonglong2*)(hb + 1 * HH + kc * 4);
                    ulonglong2 hC = *(const ulonglong2*)(hb + 2 * HH + kc * 4);
                    ulonglong2 hD = *(const ulonglong2*)(hb + 3 * HH + kc * 4);
                    fma2(ah[0][0], w0.x, hA.x); fma2(ah[0][0], w0.y, hA.y);
                    fma2(ah[0][1], w0.x, hB.x); fma2(ah[0][1], w0.y, hB.y);
                    fma2(ah[0][2], w0.x, hC.x); fma2(ah[0][2], w0.y, hC.y);
                    fma2(ah[0][3], w0.x, hD.x); fma2(ah[0][3], w0.y, hD.y);
                    fma2(ah[1][0], w1.x, hA.x); fma2(ah[1][0], w1.y, hA.y);
                    fma2(ah[1][1], w1.x, hB.x); fma2(ah[1][1], w1.y, hB.y);
                    fma2(ah[1][2], w1.x, hC.x); fma2(ah[1][2], w1.y, hC.y);
                    fma2(ah[1][3], w1.x, hD.x); fma2(ah[1][3], w1.y, hD.y);
                    fma2(ah[2][0], w2.x, hA.x); fma2(ah[2][0], w2.y, hA.y);
                    fma2(ah[2][1], w2.x, hB.x); fma2(ah[2][1], w2.y, hB.y);
                    fma2(ah[2][2], w2.x, hC.x); fma2(ah[2][2], w2.y, hC.y);
                    fma2(ah[2][3], w2.x, hD.x); fma2(ah[2][3], w2.y, hD.y);
                }
                if (i < 12) {
                    const int q = i;
                    ulonglong2 xA = *(const ulonglong2*)(xb + 0 * DP + 4 * q);
                    ulonglong2 xB = *(const ulonglong2*)(xb + 1 * DP + 4 * q);
                    ulonglong2 xC = *(const ulonglong2*)(xb + 2 * DP + 4 * q);
                    ulonglong2 xD = *(const ulonglong2*)(xb + 3 * DP + 4 * q);
                    #pragma unroll
                    for (int g = 0; g < 3; g++) {
                        unsigned long long wa = wih[g][2 * q], wb = wih[g][2 * q + 1];
                        fma2(ai[g][0], wa, xA.x); fma2(ai[g][0], wb, xA.y);
                        fma2(ai[g][1], wa, xB.x); fma2(ai[g][1], wb, xB.y);
                        fma2(ai[g][2], wa, xC.x); fma2(ai[g][2], wb, xC.y);
                        fma2(ai[g][3], wa, xD.x); fma2(ai[g][3], wb, xD.y);
                    }
                }
            }

            // ---- nonlinearity + h update, in-register ----
            float* hn = sH + nxt * (NB * HH);
            #pragma unroll
            for (int nb = 0; nb < NB; nb++) {
                float g_r = sum2(ah[0][nb]) + bh[0];
                float g_z = sum2(ah[1][nb]) + bh[1];
                float g_n = sum2(ah[2][nb]) + bh[2];
                float x_r = sum2(ai[0][nb]) + bi[0];
                float x_z = sum2(ai[1][nb]) + bi[1];
                float x_n = sum2(ai[2][nb]) + bi[2];
                float r = fast_sig(x_r + g_r);
                float z = fast_sig(x_z + g_z);
                float n = fast_tanh(x_n + r * g_n);
                float hold = hb[nb * HH + u];
                float hv = n + z * (hold - n);
                hn[nb * HH + u] = hv;
                if (t == TT - 1)
                    out[(size_t)(b0 + nb) * HH + u] = hv;
            }
        } else {
            // ---- aux: prefetch x(t+1) ----
            if (t + 1 < TT) {
                const int a = tid - NGATE;   // 0..63
                #pragma unroll
                for (int r = 0; r < 3; r++) {
                    int idx = a + r * 64;
                    if (idx < NB * DD) {
                        int nb = idx / DD, d = idx - nb * DD;
                        sX[nxt * (NB * DP) + nb * DP + d] =
                            history[(size_t)(b0 + nb) * (TT * DD) + (t + 1) * DD + d];
                    }
                }
            }
        }

        __syncthreads();   // h(t+1) + x(t+1) visible
    }
}

extern "C" void kernel_launch(void* const* d_in, const int* in_sizes, int n_in,
                              void* d_out, int out_size) {
    const float* history = (const float*)d_in[0];
    const float* W_ih    = (const float*)d_in[1];
    const float* W_hh    = (const float*)d_in[2];
    const float* b_ih    = (const float*)d_in[3];
    const float* b_hh    = (const float*)d_in[4];
    const float* h0      = (const float*)d_in[5];
    float* out = (float*)d_out;

    cudaFuncSetAttribute(gru_fused_v5,
                         cudaFuncAttributeMaxDynamicSharedMemorySize, SMEM_BYTES);
    gru_fused_v5<<<NCTA, NTHR, SMEM_BYTES>>>(history, W_ih, W_hh,
                                             b_ih, b_hh, h0, out);
}

// round 8
// speedup vs baseline: 1.0652x; 1.0652x over previous
#include <cuda_runtime.h>

// GRU_83906481094863 — v7: warp-specialized overlap (sm_100a, SIMT-only:
// harness compiles at compute_100, tcgen05 unavailable).
// B=512, T=1024, D=46, H=128. 128 CTAs x 256 threads, NB=4 batches/CTA.
// Per SMSP: 1 gate warp + 1 aux warp, different pipeline phases:
//   gate threads (tid<128, warps 0-3): unit u. hh-dot from smem W (k-chunk-
//     major LDS.128, broadcast h) -> NO wih registers -> ~140 regs, deep
//     load pipelining. Reads xp(t) (coalesced), fast nonlinearity, writes h'.
//   aux threads (tid 128-255, warps 4-7): unit a. Computes xp(t+1) =
//     W_ih x(t+1) + b_ih with W_ih in REGISTERS (crossbar-free FMA stream
//     that overlaps the gate warps' crossbar stalls), prefetches x(t+2).
// ONE __syncthreads per step. Nonlinearities via MUFU (__expf/__fdividef).

#define BB 512
#define TT 1024
#define DD 46
#define DP 48
#define HH 128
#define GG 384
#define NB 4
#define NCTA (BB/NB)   // 128
#define NTHR 256
#define NGATE 128

// Shared floats: sW[49152] | sH[2][NB][HH](1024) | sX[2][NB][DP](384)
//                | sXP[2][NB][GG](3072)
#define OFF_H  49152
#define OFF_X  50176
#define OFF_XP 50560
#define SMEM_FLOATS 53632
#define SMEM_BYTES  (SMEM_FLOATS * 4)   // 214528 < 227KB cap

__device__ __forceinline__ void fma2(unsigned long long &d,
                                     unsigned long long a,
                                     unsigned long long b) {
    asm("fma.rn.f32x2 %0, %1, %2, %0;" : "+l"(d) : "l"(a), "l"(b));
}
__device__ __forceinline__ float sum2(unsigned long long v) {
    float lo, hi;
    asm("mov.b64 {%0, %1}, %2;" : "=f"(lo), "=f"(hi) : "l"(v));
    return lo + hi;
}
__device__ __forceinline__ unsigned long long pack2(float lo, float hi) {
    unsigned long long v;
    asm("mov.b64 %0, {%1, %2};" : "=l"(v) : "f"(lo), "f"(hi));
    return v;
}
__device__ __forceinline__ float fast_sig(float x) {
    float e = __expf(-x);
    return __fdividef(1.f, 1.f + e);
}
__device__ __forceinline__ float fast_tanh(float x) {
    x = fminf(15.f, fmaxf(-15.f, x));
    float e = __expf(-2.f * x);
    return __fdividef(1.f - e, 1.f + e);
}

__global__ void __launch_bounds__(NTHR, 1) gru_ws_v7(
    const float* __restrict__ history,  // [B][T][D]
    const float* __restrict__ W_ih,     // [3H][D]
    const float* __restrict__ W_hh,     // [3H][H]
    const float* __restrict__ b_ih,     // [3H]
    const float* __restrict__ b_hh,     // [3H]
    const float* __restrict__ h0,       // [H]
    float* __restrict__ out)            // [B][H]
{
    extern __shared__ float smem[];
    float* sW  = smem;                 // float4 view: (kc*GG + j)
    float* sH  = smem + OFF_H;         // [2][NB][HH]
    float* sX  = smem + OFF_X;         // [2][NB][DP]
    float* sXP = smem + OFF_XP;        // [2][NB][GG]

    const int tid = threadIdx.x;
    const int b0  = blockIdx.x * NB;

    // ================= prologue =================
    // stage W_hh k-chunk-major
    for (int idx = tid; idx < GG * HH; idx += NTHR) {
        int j = idx >> 7, k = idx & 127;
        sW[((k >> 2) * GG + j) * 4 + (k & 3)] = W_hh[idx];
    }
    // h(0)
    for (int idx = tid; idx < NB * HH; idx += NTHR)
        sH[idx] = h0[idx & 127];
    // zero x pads (both buffers)
    if (tid < 16) {
        int buf = tid >> 3, nb = (tid >> 1) & 3, d = DD + (tid & 1);
        sX[buf * (NB * DP) + nb * DP + d] = 0.f;
    }
    // x(0) -> buf0, x(1) -> buf1
    for (int idx = tid; idx < NB * DD; idx += NTHR) {
        int nb = idx / DD, d = idx - nb * DD;
        sX[nb * DP + d]            = history[(size_t)(b0 + nb) * (TT * DD) + d];
        sX[NB * DP + nb * DP + d]  = history[(size_t)(b0 + nb) * (TT * DD) + DD + d];
    }

    // per-role private state
    const bool is_gate = (tid < NGATE);
    const int  u  = tid;                 // gate unit
    const int  a  = tid - NGATE;         // aux unit
    unsigned long long wih[3][24];       // aux only
    float bi[3], bh[3];
    if (is_gate) {
        #pragma unroll
        for (int g = 0; g < 3; g++) bh[g] = b_hh[u + g * HH];
    } else {
        #pragma unroll
        for (int g = 0; g < 3; g++) {
            const int j = a + g * HH;
            bi[g] = b_ih[j];
            #pragma unroll
            for (int p = 0; p < 23; p++)
                wih[g][p] = pack2(W_ih[j * DD + 2 * p], W_ih[j * DD + 2 * p + 1]);
            wih[g][23] = 0ull;
        }
    }
    const ulonglong2* wrow0 = (const ulonglong2*)sW + u;      // gate rows
    const ulonglong2* wrow1 = wrow0 + HH;
    const ulonglong2* wrow2 = wrow0 + 2 * HH;

    __syncthreads();

    // pre-step: aux computes xp(0) from x buf0 into sXP buf0
    if (!is_gate) {
        const float* xb = sX;            // buf 0 = x(0)
        unsigned long long ai[3][NB];
        #pragma unroll
        for (int g = 0; g < 3; g++)
            #pragma unroll
            for (int nb = 0; nb < NB; nb++) ai[g][nb] = 0ull;
        #pragma unroll
        for (int q = 0; q < 12; q++) {
            ulonglong2 xA = *(const ulonglong2*)(xb + 0 * DP + 4 * q);
            ulonglong2 xB = *(const ulonglong2*)(xb + 1 * DP + 4 * q);
            ulonglong2 xC = *(const ulonglong2*)(xb + 2 * DP + 4 * q);
            ulonglong2 xD = *(const ulonglong2*)(xb + 3 * DP + 4 * q);
            #pragma unroll
            for (int g = 0; g < 3; g++) {
                unsigned long long wa = wih[g][2 * q], wb = wih[g][2 * q + 1];
                fma2(ai[g][0], wa, xA.x); fma2(ai[g][0], wb, xA.y);
                fma2(ai[g][1], wa, xB.x); fma2(ai[g][1], wb, xB.y);
                fma2(ai[g][2], wa, xC.x); fma2(ai[g][2], wb, xC.y);
                fma2(ai[g][3], wa, xD.x); fma2(ai[g][3], wb, xD.y);
            }
        }
        #pragma unroll
        for (int g = 0; g < 3; g++)
            #pragma unroll
            for (int nb = 0; nb < NB; nb++)
                sXP[nb * GG + g * HH + a] = sum2(ai[g][nb]) + bi[g];
    }
    __syncthreads();

    // ================= main loop =================
    for (int t = 0; t < TT; t++) {
        const int cur = t & 1, nxt = cur ^ 1;

        if (is_gate) {
            // ---- hh-dot over h(t) ----
            const float* hb = sH + cur * (NB * HH);
            unsigned long long ah[3][NB];
            #pragma unroll
            for (int g = 0; g < 3; g++)
                #pragma unroll
                for (int nb = 0; nb < NB; nb++) ah[g][nb] = 0ull;

            #pragma unroll 8
            for (int kc = 0; kc < 32; kc++) {
                ulonglong2 w0 = wrow0[kc * GG];
                ulonglong2 w1 = wrow1[kc * GG];
                ulonglong2 w2 = wrow2[kc * GG];
                ulonglong2 hA = *(const ulonglong2*)(hb + 0 * HH + kc * 4);
                ulonglong2 hB = *(const ulonglong2*)(hb + 1 * HH + kc * 4);
                ulonglong2 hC = *(const ulonglong2*)(hb + 2 * HH + kc * 4);
                ulonglong2 hD = *(const ulonglong2*)(hb + 3 * HH + kc * 4);
                fma2(ah[0][0], w0.x, hA.x); fma2(ah[0][0], w0.y, hA.y);
                fma2(ah[0][1], w0.x, hB.x); fma2(ah[0][1], w0.y, hB.y);
                fma2(ah[0][2], w0.x, hC.x); fma2(ah[0][2], w0.y, hC.y);
                fma2(ah[0][3], w0.x, hD.x); fma2(ah[0][3], w0.y, hD.y);
                fma2(ah[1][0], w1.x, hA.x); fma2(ah[1][0], w1.y, hA.y);
                fma2(ah[1][1], w1.x, hB.x); fma2(ah[1][1], w1.y, hB.y);
                fma2(ah[1][2], w1.x, hC.x); fma2(ah[1][2], w1.y, hC.y);
                fma2(ah[1][3], w1.x, hD.x); fma2(ah[1][3], w1.y, hD.y);
                fma2(ah[2][0], w2.x, hA.x); fma2(ah[2][0], w2.y, hA.y);
                fma2(ah[2][1], w2.x, hB.x); fma2(ah[2][1], w2.y, hB.y);
                fma2(ah[2][2], w2.x, hC.x); fma2(ah[2][2], w2.y, hC.y);
                fma2(ah[2][3], w2.x, hD.x); fma2(ah[2][3], w2.y, hD.y);
            }

            // ---- xp(t) + nonlinearity + h update ----
            const float* xp = sXP + cur * (NB * GG);
            float* hn = sH + nxt * (NB * HH);
            #pragma unroll
            for (int nb = 0; nb < NB; nb++) {
                float x_r = xp[nb * GG + u];
                float x_z = xp[nb * GG + HH + u];
                float x_n = xp[nb * GG + 2 * HH + u];
                float g_r = sum2(ah[0][nb]) + bh[0];
                float g_z = sum2(ah[1][nb]) + bh[1];
                float g_n = sum2(ah[2][nb]) + bh[2];
                float r = fast_sig(x_r + g_r);
                float z = fast_sig(x_z + g_z);
                float n = fast_tanh(x_n + r * g_n);
                float hv = n + z * (hb[nb * HH + u] - n);
                hn[nb * HH + u] = hv;
                if (t == TT - 1)
                    out[(size_t)(b0 + nb) * HH + u] = hv;
            }
        } else {
            // ---- aux: xp(t+1) from x(t+1); prefetch x(t+2) ----
            if (t + 2 < TT) {
                // load x(t+2) into buffer (t&1)  [free: x(t) no longer needed]
                #pragma unroll
                for (int r = 0; r < 2; r++) {
                    int idx = a + r * 128;
                    if (idx < NB * DD) {
                        int nb = idx / DD, d = idx - nb * DD;
                        sX[cur * (NB * DP) + nb * DP + d] =
                            history[(size_t)(b0 + nb) * (TT * DD) + (t + 2) * DD + d];
                    }
                }
            }
            if (t + 1 < TT) {
                const float* xb = sX + nxt * (NB * DP);   // x(t+1)
                unsigned long long ai[3][NB];
                #pragma unroll
                for (int g = 0; g < 3; g++)
                    #pragma unroll
                    for (int nb = 0; nb < NB; nb++) ai[g][nb] = 0ull;
                #pragma unroll
                for (int q = 0; q < 12; q++) {
                    ulonglong2 xA = *(const ulonglong2*)(xb + 0 * DP + 4 * q);
                    ulonglong2 xB = *(const ulonglong2*)(xb + 1 * DP + 4 * q);
                    ulonglong2 xC = *(const ulonglong2*)(xb + 2 * DP + 4 * q);
                    ulonglong2 xD = *(const ulonglong2*)(xb + 3 * DP + 4 * q);
                    #pragma unroll
                    for (int g = 0; g < 3; g++) {
                        unsigned long long wa = wih[g][2 * q], wb = wih[g][2 * q + 1];
                        fma2(ai[g][0], wa, xA.x); fma2(ai[g][0], wb, xA.y);
                        fma2(ai[g][1], wa, xB.x); fma2(ai[g][1], wb, xB.y);
                        fma2(ai[g][2], wa, xC.x); fma2(ai[g][2], wb, xC.y);
                        fma2(ai[g][3], wa, xD.x); fma2(ai[g][3], wb, xD.y);
                    }
                }
                float* xpn = sXP + nxt * (NB * GG);
                #pragma unroll
                for (int g = 0; g < 3; g++)
                    #pragma unroll
                    for (int nb = 0; nb < NB; nb++)
                        xpn[nb * GG + g * HH + a] = sum2(ai[g][nb]) + bi[g];
            }
        }

        __syncthreads();   // h(t+1), xp(t+1), x(t+2) all published
    }
}

extern "C" void kernel_launch(void* const* d_in, const int* in_sizes, int n_in,
                              void* d_out, int out_size) {
    const float* history = (const float*)d_in[0];
    const float* W_ih    = (const float*)d_in[1];
    const float* W_hh    = (const float*)d_in[2];
    const float* b_ih    = (const float*)d_in[3];
    const float* b_hh    = (const float*)d_in[4];
    const float* h0      = (const float*)d_in[5];
    float* out = (float*)d_out;

    cudaFuncSetAttribute(gru_ws_v7,
                         cudaFuncAttributeMaxDynamicSharedMemorySize, SMEM_BYTES);
    gru_ws_v7<<<NCTA, NTHR, SMEM_BYTES>>>(history, W_ih, W_hh,
                                          b_ih, b_hh, h0, out);
}